// round 4
// baseline (speedup 1.0000x reference)
#include <cuda_runtime.h>
#include <cuda_bf16.h>

// WeightedBiasEncoder: out[B*H, N+1, N+1]
//   out[bh][0][*] = token[h];  out[bh][r][0] = token[h] (r>=1)
//   out[bh][r][c] = emb[spatial[(b*N + r-1)*N + (c-1)]][h]   (r,c >= 1)
//
// H==8 fast path: emb row for index s = two float4s -> 1 LDG + 2 LDS.128
// serve all 8 head planes. Persistent row-pair loop per block amortizes the
// smem table load; next pair's spatial indices are prefetched while the
// current pair is gathered/stored. Streaming hints (__ldcs/__stcs) keep the
// 135MB write stream from thrashing L2.

#define TPB 128
#define GX  64            // row-pair blocks per graph

__global__ __launch_bounds__(TPB) void wbe_fast8(
    const int*   __restrict__ spatial,   // [B*N*N]
    const float* __restrict__ emb,       // [SP1, 8]
    const float* __restrict__ token,     // [8]
    float*       __restrict__ out,       // [B*8, N+1, N+1]
    int N, int SP1)
{
    __shared__ float4 emb4s[272];        // supports SP1 <= 136
    const int tid = threadIdx.x;
    const int n4  = SP1 * 2;
    const float4* __restrict__ emb4g = (const float4*)emb;
    for (int i = tid; i < n4; i += TPB) emb4s[i] = emb4g[i];
    __syncthreads();

    const int bx = blockIdx.x;           // 0..GX-1
    const int b  = blockIdx.y;
    const unsigned P  = (unsigned)N + 1u;
    const unsigned P2 = P * P;
    const unsigned planeb = (unsigned)(b * 8) * P2;
    const int npairs = N >> 1;
    const int iters  = npairs / GX;

    if (bx == 0) {
        // graph-token row (row 0) for all 8 heads
        #pragma unroll
        for (int h = 0; h < 8; h++) {
            const float tv = token[h];
            for (unsigned c = tid; c < P; c += TPB)
                __stcs(&out[planeb + (unsigned)h * P2 + c], tv);
        }
    }

    const float tokv = token[tid & 7];   // used by tid<16 for column 0

    // ---- prefetch pair 0 ----
    int sc[8];
    {
        const int* __restrict__ sr =
            spatial + ((size_t)b * (size_t)N + (size_t)(2 * bx)) * (size_t)N;
        #pragma unroll
        for (int k = 0; k < 4; k++) {
            sc[k]     = __ldcs(sr + tid + k * TPB);
            sc[4 + k] = __ldcs(sr + N + tid + k * TPB);
        }
    }

    for (int it = 0; it < iters; it++) {
        const int p = bx + it * GX;

        // prefetch next pair (clamped reload of current on the last iter)
        int pn = p + GX;
        if (pn >= npairs) pn = p;
        const int* __restrict__ srn =
            spatial + ((size_t)b * (size_t)N + (size_t)(2 * pn)) * (size_t)N;
        int sn[8];
        #pragma unroll
        for (int k = 0; k < 4; k++) {
            sn[k]     = __ldcs(srn + tid + k * TPB);
            sn[4 + k] = __ldcs(srn + N + tid + k * TPB);
        }

        const int r0 = 2 * p + 1;
        // graph-token column (col 0), both rows, all heads
        if (tid < 16) {
            const int h = tid & 7, dr = tid >> 3;
            __stcs(&out[planeb + (unsigned)h * P2 + (unsigned)(r0 + dr) * P], tokv);
        }

        float* __restrict__ o0 = out + planeb + (unsigned)r0 * P + 1;
        float* __restrict__ o1 = o0 + P;

        #pragma unroll
        for (int k = 0; k < 4; k++) {
            const int c = tid + k * TPB;
            {
                const float4 va = emb4s[2 * sc[k]];
                const float4 vb = emb4s[2 * sc[k] + 1];
                float* __restrict__ q = o0 + c;
                __stcs(q + 0u * P2, va.x);  __stcs(q + 1u * P2, va.y);
                __stcs(q + 2u * P2, va.z);  __stcs(q + 3u * P2, va.w);
                __stcs(q + 4u * P2, vb.x);  __stcs(q + 5u * P2, vb.y);
                __stcs(q + 6u * P2, vb.z);  __stcs(q + 7u * P2, vb.w);
            }
            {
                const float4 va = emb4s[2 * sc[4 + k]];
                const float4 vb = emb4s[2 * sc[4 + k] + 1];
                float* __restrict__ q = o1 + c;
                __stcs(q + 0u * P2, va.x);  __stcs(q + 1u * P2, va.y);
                __stcs(q + 2u * P2, va.z);  __stcs(q + 3u * P2, va.w);
                __stcs(q + 4u * P2, vb.x);  __stcs(q + 5u * P2, vb.y);
                __stcs(q + 6u * P2, vb.z);  __stcs(q + 7u * P2, vb.w);
            }
        }

        #pragma unroll
        for (int k = 0; k < 8; k++) sc[k] = sn[k];
    }
}

// Generic fallback (H != 8, table too big, or N % 256 != 0).
#define G_ROWS 4
#define G_TPB 256

__global__ __launch_bounds__(G_TPB) void wbe_generic(
    const int*   __restrict__ spatial,
    const float* __restrict__ emb,
    const float* __restrict__ token,
    float*       __restrict__ out,
    int N, int H, int SP1)
{
    __shared__ float emb_s[4096];
    const int tid = threadIdx.x;
    int total = SP1 * H;
    if (total > 4096) total = 4096;
    for (int idx = tid; idx < total; idx += G_TPB) {
        int h = idx / SP1;
        int s = idx - h * SP1;
        emb_s[idx] = emb[s * H + h];
    }
    __syncthreads();

    const unsigned bh = blockIdx.y;
    const int h = (int)(bh % (unsigned)H);
    const int b = (int)(bh / (unsigned)H);
    const float tokv = token[h];
    const unsigned P  = (unsigned)N + 1u;
    const unsigned P2 = P * P;
    const float* __restrict__ eh = emb_s + h * SP1;
    float* __restrict__ plane = out + (size_t)bh * (size_t)P2;

    #pragma unroll
    for (int rr = 0; rr < G_ROWS; rr++) {
        const unsigned r = blockIdx.x * G_ROWS + rr;
        if (r >= P) return;
        float* __restrict__ orow = plane + (size_t)r * P;
        if (r == 0) {
            for (unsigned c = tid; c < P; c += G_TPB) orow[c] = tokv;
        } else {
            if (tid == 0) orow[0] = tokv;
            const int* __restrict__ srow =
                spatial + ((size_t)b * (size_t)N + (size_t)(r - 1)) * (size_t)N;
            for (unsigned c = tid; c < (unsigned)N; c += G_TPB)
                orow[1 + c] = eh[srow[c]];
        }
    }
}

extern "C" void kernel_launch(void* const* d_in, const int* in_sizes, int n_in,
                              void* d_out, int out_size)
{
    const int*   spatial = (const int*)  d_in[0];
    const float* emb     = (const float*)d_in[n_in - 2];
    const float* token   = (const float*)d_in[n_in - 1];

    const int E         = in_sizes[0];          // B*N*N
    const int num_nodes = in_sizes[2];          // B*N
    const int H         = in_sizes[n_in - 1];
    const int SP1       = in_sizes[n_in - 2] / H;
    const int N         = E / num_nodes;
    const int B         = num_nodes / N;
    const int P         = N + 1;

    if (H == 8 && SP1 * 2 <= 272 && (N % 256) == 0) {
        dim3 grid((unsigned)GX, (unsigned)B);
        wbe_fast8<<<grid, TPB>>>(spatial, emb, token, (float*)d_out, N, SP1);
    } else {
        dim3 grid((P + G_ROWS - 1) / G_ROWS, (unsigned)(B * H));
        wbe_generic<<<grid, G_TPB>>>(spatial, emb, token, (float*)d_out, N, H, SP1);
    }
}

// round 5
// speedup vs baseline: 1.3853x; 1.3853x over previous
#include <cuda_runtime.h>
#include <cuda_bf16.h>

// WeightedBiasEncoder: out[B*H, N+1, N+1]
//   out[bh][0][*] = token[h];  out[bh][r][0] = token[h] (r>=1)
//   out[bh][r][c] = emb[spatial[(b*N + r-1)*N + (c-1)]][h]   (r,c >= 1)
//
// H==8, N==512 fast path: emb row for index s = 8 floats = two float4s.
// Table stored in SMEM with a 48-byte entry stride: bank group of entry s is
// 12*s mod 32, so two lanes conflict only when s == s' (mod 8) — the best
// achievable for 16B-granular LDS, vs mod-4 at the natural 32B stride.
// One block = 2 interior rows (128 threads each), 4 front-batched spatial
// LDGs per thread for MLP.

#define TPB 256
#define ESTRIDE 12   // words per table entry (48 B)

__global__ __launch_bounds__(TPB) void wbe_fast8(
    const int*   __restrict__ spatial,   // [B*N*N]
    const float* __restrict__ emb,       // [SP1, 8]
    const float* __restrict__ token,     // [8]
    float*       __restrict__ out,       // [B*8, N+1, N+1]
    int N, int SP1)
{
    __shared__ __align__(16) float emb_s[ESTRIDE * 136];  // SP1 <= 136
    const int tid = threadIdx.x;
    for (int i = tid; i < SP1 * 8; i += TPB) {
        const int s = i >> 3, h = i & 7;
        emb_s[ESTRIDE * s + h] = emb[i];
    }
    __syncthreads();

    const int bx = blockIdx.x;
    const int b  = blockIdx.y;
    const unsigned P  = (unsigned)N + 1u;
    const unsigned P2 = P * P;
    const unsigned planeb = (unsigned)(b * 8) * P2;

    if (bx == 0) {
        // graph-token row (row 0) for all 8 heads
        #pragma unroll
        for (int h = 0; h < 8; h++) {
            const float tv = token[h];
            for (unsigned c = tid; c < P; c += TPB)
                out[planeb + (unsigned)h * P2 + c] = tv;
        }
        return;
    }

    // two interior rows per block: threads 0-127 -> r0, 128-255 -> r0+1
    const int r  = 2 * (bx - 1) + 1 + (tid >> 7);
    const int ct = tid & 127;

    // graph-token column (col 0) for this row, all 8 heads
    if (ct < 8)
        out[planeb + (unsigned)ct * P2 + (unsigned)r * P] = token[ct];

    const int* __restrict__ srow =
        spatial + ((size_t)b * (size_t)N + (size_t)(r - 1)) * (size_t)N;
    float* __restrict__ o = out + planeb + (unsigned)r * P + 1;

    // front-batch 4 independent spatial loads (N == 512 -> 4 slots of 128)
    int s[4];
    #pragma unroll
    for (int k = 0; k < 4; k++)
        s[k] = __ldg(srow + ct + k * 128);

    #pragma unroll
    for (int k = 0; k < 4; k++) {
        const float* __restrict__ e = emb_s + ESTRIDE * s[k];
        const float4 va = *(const float4*)(e);      // heads 0..3
        const float4 vb = *(const float4*)(e + 4);  // heads 4..7
        float* __restrict__ q = o + ct + k * 128;
        q[0u * P2] = va.x;  q[1u * P2] = va.y;
        q[2u * P2] = va.z;  q[3u * P2] = va.w;
        q[4u * P2] = vb.x;  q[5u * P2] = vb.y;
        q[6u * P2] = vb.z;  q[7u * P2] = vb.w;
    }
}

// Generic fallback (H != 8, table too big, or N != 512).
#define G_ROWS 4
#define G_TPB 256

__global__ __launch_bounds__(G_TPB) void wbe_generic(
    const int*   __restrict__ spatial,
    const float* __restrict__ emb,
    const float* __restrict__ token,
    float*       __restrict__ out,
    int N, int H, int SP1)
{
    __shared__ float emb_s[4096];
    const int tid = threadIdx.x;
    int total = SP1 * H;
    if (total > 4096) total = 4096;
    for (int idx = tid; idx < total; idx += G_TPB) {
        int h = idx / SP1;
        int s = idx - h * SP1;
        emb_s[idx] = emb[s * H + h];
    }
    __syncthreads();

    const unsigned bh = blockIdx.y;
    const int h = (int)(bh % (unsigned)H);
    const int b = (int)(bh / (unsigned)H);
    const float tokv = token[h];
    const unsigned P  = (unsigned)N + 1u;
    const unsigned P2 = P * P;
    const float* __restrict__ eh = emb_s + h * SP1;
    float* __restrict__ plane = out + (size_t)bh * (size_t)P2;

    #pragma unroll
    for (int rr = 0; rr < G_ROWS; rr++) {
        const unsigned r = blockIdx.x * G_ROWS + rr;
        if (r >= P) return;
        float* __restrict__ orow = plane + (size_t)r * P;
        if (r == 0) {
            for (unsigned c = tid; c < P; c += G_TPB) orow[c] = tokv;
        } else {
            if (tid == 0) orow[0] = tokv;
            const int* __restrict__ srow =
                spatial + ((size_t)b * (size_t)N + (size_t)(r - 1)) * (size_t)N;
            for (unsigned c = tid; c < (unsigned)N; c += G_TPB)
                orow[1 + c] = eh[srow[c]];
        }
    }
}

extern "C" void kernel_launch(void* const* d_in, const int* in_sizes, int n_in,
                              void* d_out, int out_size)
{
    const int*   spatial = (const int*)  d_in[0];
    const float* emb     = (const float*)d_in[n_in - 2];
    const float* token   = (const float*)d_in[n_in - 1];

    const int E         = in_sizes[0];          // B*N*N
    const int num_nodes = in_sizes[2];          // B*N
    const int H         = in_sizes[n_in - 1];
    const int SP1       = in_sizes[n_in - 2] / H;
    const int N         = E / num_nodes;
    const int B         = num_nodes / N;
    const int P         = N + 1;

    if (H == 8 && SP1 <= 136 && N == 512) {
        dim3 grid((unsigned)(N / 2 + 1), (unsigned)B);
        wbe_fast8<<<grid, TPB>>>(spatial, emb, token, (float*)d_out, N, SP1);
    } else {
        dim3 grid((P + G_ROWS - 1) / G_ROWS, (unsigned)(B * H));
        wbe_generic<<<grid, G_TPB>>>(spatial, emb, token, (float*)d_out, N, H, SP1);
    }
}